// round 14
// baseline (speedup 1.0000x reference)
#include <cuda_runtime.h>
#include <cuda_bf16.h>
#include <cstdint>

#define D_   3072
#define H_   1024
#define Z_   32
#define BS_  128
#define NN_  32
#define MNN  4096   // BS_*NN_
#define MALL 4224   // BS_ + MNN
#define H1ROWS 2176  // centers(128) + neighbors 0..2047
#define H1NB   2048  // neighbor rows in half 1

// ---------------------------------------------------------------------------
// Static scratch (allocation-free rule)
// ---------------------------------------------------------------------------
__device__ __align__(16) __nv_bfloat16 g_xa[MALL * D_];    // [x_c; x_nn] bf16
__device__ __align__(16) __nv_bfloat16 g_h1b[MALL * H_];   // enc h1
__device__ __align__(16) __nv_bfloat16 g_h2b[MALL * H_];   // enc h2
__device__ __align__(16) __nv_bfloat16 g_t1[MNN * H_];     // jvp t1
__device__ __align__(16) __nv_bfloat16 g_t2[MNN * H_];     // jvp t2
__device__ __align__(16) __nv_bfloat16 g_We1t[H_ * D_];    // We1^T [N,K] bf16
__device__ __align__(16) __nv_bfloat16 g_We2t[H_ * H_];
__device__ __align__(16) __nv_bfloat16 g_Wd1t[H_ * 64];    // Wd1^T, K pad 32->64
__device__ __align__(16) __nv_bfloat16 g_Wd2t[H_ * H_];
__device__ __align__(16) __nv_bfloat16 g_Wd3t[D_ * H_];
__device__ __align__(16) __nv_bfloat16 g_zcb[BS_ * 64];    // z_c bf16, padded
__device__ __align__(16) __nv_bfloat16 g_dzb[MNN * 64];    // dz bf16, padded
__device__ __align__(16) __nv_bfloat16 g_h1cb[BS_ * H_];   // center dec h1 (mask1)
__device__ __align__(16) __nv_bfloat16 g_h2cb[BS_ * H_];   // center dec h2 (mask2)
__device__ float g_recon[BS_ * D_];
__device__ float g_w[MNN];
__device__ float g_lpart[768];

// ---------------------------------------------------------------------------
// PTX helpers (plain sm_80+ PTX — assembles for target sm_103)
// ---------------------------------------------------------------------------
__device__ __forceinline__ uint32_t smem_u32(const void* p)
{
    uint32_t a;
    asm("{ .reg .u64 t; cvta.to.shared.u64 t, %1; cvt.u32.u64 %0, t; }"
        : "=r"(a) : "l"(p));
    return a;
}
#define CP_ASYNC16(dst, src) \
    asm volatile("cp.async.cg.shared.global [%0], [%1], 16;" \
                 :: "r"(dst), "l"(src) : "memory")
#define CP_COMMIT()  asm volatile("cp.async.commit_group;" ::: "memory")
#define CP_WAIT1()   asm volatile("cp.async.wait_group 1;" ::: "memory")

__device__ __forceinline__ void ldmx4(uint32_t* r, uint32_t addr)
{
    asm volatile("ldmatrix.sync.aligned.m8n8.x4.shared.b16 {%0,%1,%2,%3}, [%4];"
                 : "=r"(r[0]), "=r"(r[1]), "=r"(r[2]), "=r"(r[3]) : "r"(addr));
}
__device__ __forceinline__ void mma_bf16(float* c, const uint32_t* a,
                                         uint32_t b0, uint32_t b1)
{
    asm volatile(
        "mma.sync.aligned.m16n8k16.row.col.f32.bf16.bf16.f32 "
        "{%0,%1,%2,%3}, {%4,%5,%6,%7}, {%8,%9}, {%0,%1,%2,%3};"
        : "+f"(c[0]), "+f"(c[1]), "+f"(c[2]), "+f"(c[3])
        : "r"(a[0]), "r"(a[1]), "r"(a[2]), "r"(a[3]), "r"(b0), "r"(b1));
}
__device__ __forceinline__ uint32_t sw128(uint32_t o) { return o ^ ((o >> 3) & 0x70); }

// ---------------------------------------------------------------------------
// Warp-MMA GEMM: C[M,N] = A[M,K] @ Bt[N,K]^T  (bf16 in, fp32 accum)
// Block 128x128, BK=64, 4 warps (2x2), warp tile 64x64 (mma:ldsm = 4:1).
// 128 threads, 2 CTAs/SM. 3-stage cp.async, prefetch distance 2.
// rowoff: global-row offset of A's first row (for mask/recon/w/xnn indexing)
// EPI: 1 bias+relu->bf16 | 3 bias->f32 | 4 mask(bf16>0)->bf16 | 5 fused loss
// ---------------------------------------------------------------------------
static constexpr int STAGE_BYTES = 32768;           // A 16KB + B 16KB
static constexpr int SMEM_BYTES  = 3 * STAGE_BYTES; // 96KB -> 2 CTAs/SM

template <int EPI>
__global__ void __launch_bounds__(128, 2) tgemm(
    const __nv_bfloat16* __restrict__ A, const __nv_bfloat16* __restrict__ Bt,
    int K, int N, int rowoff,
    __nv_bfloat16* __restrict__ Cb, float* __restrict__ Cf,
    const float* __restrict__ bias, const __nv_bfloat16* __restrict__ maskp,
    const float* __restrict__ xnn, const float* __restrict__ recon,
    const float* __restrict__ wrow, float* __restrict__ lpart)
{
    extern __shared__ __align__(128) char smem[];
    const uint32_t sb = smem_u32(smem);
    const int tid = threadIdx.x, lane = tid & 31, wid = tid >> 5;
    const int wm = wid & 1, wn = wid >> 1;           // 2 x 2 warp grid
    const int rb = blockIdx.y << 7, cbase = blockIdx.x << 7;

    float acc[4][8][4];
#pragma unroll
    for (int i = 0; i < 4; i++)
#pragma unroll
        for (int j = 0; j < 8; j++)
#pragma unroll
            for (int q = 0; q < 4; q++) acc[i][j][q] = 0.f;

    const int nk = K >> 6;

    // cp.async mapping: 128 threads, 16 rows per i-step, 8 x 16B per row
    const int ldrow = tid >> 3;           // 0..15, +16 per i
    const int ldc   = tid & 7;
    const __nv_bfloat16* Abase = A  + (size_t)(rb + ldrow) * K + ldc * 8;
    const __nv_bfloat16* Bbase = Bt + (size_t)(cbase + ldrow) * K + ldc * 8;

    const int aBase = (wm * 64 + (lane & 15)) * 128 + ((lane >> 4) * 16);
    const int bBase = (wn * 64 + (lane & 7) + ((lane >> 4) * 8)) * 128
                    + (((lane >> 3) & 1) * 16);

#pragma unroll
    for (int s = 0; s < 2; s++) {
        if (s < nk) {
            const uint32_t sa = sb + s * STAGE_BYTES;
#pragma unroll
            for (int i = 0; i < 8; i++) {
                uint32_t sw = sw128((ldrow + i * 16) * 128 + ldc * 16);
                CP_ASYNC16(sa + sw,         Abase + (size_t)(i * 16) * K + s * 64);
                CP_ASYNC16(sa + 16384 + sw, Bbase + (size_t)(i * 16) * K + s * 64);
            }
        }
        CP_COMMIT();
    }

    for (int kc = 0; kc < nk; kc++) {
        CP_WAIT1();
        __syncthreads();

        const int nx = kc + 2;
        if (nx < nk) {
            const uint32_t sn = sb + (nx % 3) * STAGE_BYTES;
#pragma unroll
            for (int i = 0; i < 8; i++) {
                uint32_t sw = sw128((ldrow + i * 16) * 128 + ldc * 16);
                CP_ASYNC16(sn + sw,         Abase + (size_t)(i * 16) * K + nx * 64);
                CP_ASYNC16(sn + 16384 + sw, Bbase + (size_t)(i * 16) * K + nx * 64);
            }
        }
        CP_COMMIT();

        const uint32_t sa = sb + (kc % 3) * STAGE_BYTES;
        const uint32_t sbB = sa + 16384;
#pragma unroll
        for (int ks = 0; ks < 4; ks++) {
            uint32_t a[4][4], b[4][4];
#pragma unroll
            for (int mi = 0; mi < 4; mi++)
                ldmx4(a[mi], sa + sw128(aBase + mi * 2048 + ks * 32));
#pragma unroll
            for (int g = 0; g < 4; g++)
                ldmx4(b[g], sbB + sw128(bBase + g * 2048 + ks * 32));
#pragma unroll
            for (int mi = 0; mi < 4; mi++)
#pragma unroll
                for (int nj = 0; nj < 8; nj++)
                    mma_bf16(acc[mi][nj], a[mi],
                             b[nj >> 1][(nj & 1) * 2], b[nj >> 1][(nj & 1) * 2 + 1]);
        }
    }

    // ---- epilogue
    const int er0 = wm * 64 + (lane >> 2);
    const int ec0 = wn * 64 + (lane & 3) * 2;
    float lsum = 0.f;
#pragma unroll
    for (int mi = 0; mi < 4; mi++) {
#pragma unroll
        for (int half = 0; half < 2; half++) {
            const int r  = rb + er0 + mi * 16 + half * 8;
            const int gr = r + rowoff;
#pragma unroll
            for (int nj = 0; nj < 8; nj++) {
                const int cc = cbase + ec0 + nj * 8;
                float v0 = acc[mi][nj][half * 2];
                float v1 = acc[mi][nj][half * 2 + 1];
                if (EPI == 1) {
                    v0 = fmaxf(v0 + bias[cc], 0.f);
                    v1 = fmaxf(v1 + bias[cc + 1], 0.f);
                    *(__nv_bfloat162*)(Cb + (size_t)r * N + cc) =
                        __floats2bfloat162_rn(v0, v1);
                } else if (EPI == 3) {
                    Cf[(size_t)r * N + cc]     = v0 + bias[cc];
                    Cf[(size_t)r * N + cc + 1] = v1 + bias[cc + 1];
                } else if (EPI == 4) {
                    const __nv_bfloat16* mr = maskp + (size_t)(gr >> 5) * N + cc;
                    v0 = (__bfloat162float(mr[0]) > 0.f) ? v0 : 0.f;
                    v1 = (__bfloat162float(mr[1]) > 0.f) ? v1 : 0.f;
                    *(__nv_bfloat162*)(Cb + (size_t)r * N + cc) =
                        __floats2bfloat162_rn(v0, v1);
                } else {   // EPI 5: fused weighted squared error
                    const float* xr = xnn   + (size_t)gr * N + cc;
                    const float* rr = recon + (size_t)(gr >> 5) * N + cc;
                    float e0 = xr[0] - rr[0] - v0;
                    float e1 = xr[1] - rr[1] - v1;
                    lsum += wrow[gr] * (e0 * e0 + e1 * e1);
                }
            }
        }
    }
    if (EPI == 5) {
#pragma unroll
        for (int o = 16; o; o >>= 1) lsum += __shfl_down_sync(0xffffffffu, lsum, o);
        __shared__ float red[4];
        if ((tid & 31) == 0) red[wid] = lsum;
        __syncthreads();
        if (tid == 0)
            lpart[blockIdx.y * gridDim.x + blockIdx.x] =
                red[0] + red[1] + red[2] + red[3];
    }
}

// ---------------------------------------------------------------------------
// Fused conversion + binary-kernel weights (one block per batch row).
// ---------------------------------------------------------------------------
__global__ void __launch_bounds__(256) conv_x_w(
    const float* __restrict__ xc, const float* __restrict__ xnn, int roff)
{
    const int r = blockIdx.x + roff;
    if (r < BS_) {
        const float4* src = (const float4*)(xc + (size_t)r * D_);
        __nv_bfloat162* dst = (__nv_bfloat162*)(g_xa + (size_t)r * D_);
#pragma unroll
        for (int i = 0; i < 3; i++) {
            float4 v = src[threadIdx.x + i * 256];
            dst[(threadIdx.x + i * 256) * 2]     = __floats2bfloat162_rn(v.x, v.y);
            dst[(threadIdx.x + i * 256) * 2 + 1] = __floats2bfloat162_rn(v.z, v.w);
        }
        return;
    }
    const int rn = r - BS_;
    const float4* src = (const float4*)(xnn + (size_t)rn * D_);
    const float4* cen = (const float4*)(xc + (size_t)(rn >> 5) * D_);
    __nv_bfloat162* dst = (__nv_bfloat162*)(g_xa + (size_t)r * D_);
    float s = 0.f;
#pragma unroll
    for (int i = 0; i < 3; i++) {
        float4 v = src[threadIdx.x + i * 256];
        float4 c = cen[threadIdx.x + i * 256];
        dst[(threadIdx.x + i * 256) * 2]     = __floats2bfloat162_rn(v.x, v.y);
        dst[(threadIdx.x + i * 256) * 2 + 1] = __floats2bfloat162_rn(v.z, v.w);
        float dx = v.x - c.x, dy = v.y - c.y, dz2 = v.z - c.z, dw = v.w - c.w;
        s += dx * dx + dy * dy + dz2 * dz2 + dw * dw;
    }
#pragma unroll
    for (int o = 16; o; o >>= 1) s += __shfl_down_sync(0xffffffffu, s, o);
    __shared__ float red[8];
    if ((threadIdx.x & 31) == 0) red[threadIdx.x >> 5] = s;
    __syncthreads();
    if (threadIdx.x == 0) {
        float t = 0.f;
#pragma unroll
        for (int i = 0; i < 8; i++) t += red[i];
        g_w[rn] = (t > 1e-24f) ? 1.0f : 0.5f;
    }
}

// W[K,N] f32 -> Wt[N,Kp] bf16 (zero pad K..Kp)
__global__ void __launch_bounds__(256) transpose_bf16(
    const float* __restrict__ in, __nv_bfloat16* __restrict__ out,
    int K, int N, int Kp)
{
    __shared__ float tile[32][33];
    const int kb = blockIdx.y * 32, nb = blockIdx.x * 32;
    const int tx = threadIdx.x & 31, ty = threadIdx.x >> 5;
#pragma unroll
    for (int i = 0; i < 32; i += 8) {
        int k = kb + ty + i, n = nb + tx;
        tile[ty + i][tx] = (k < K && n < N) ? in[(size_t)k * N + n] : 0.f;
    }
    __syncthreads();
#pragma unroll
    for (int i = 0; i < 32; i += 8) {
        int n = nb + ty + i, k = kb + tx;
        out[(size_t)n * Kp + k] = __float2bfloat16(tile[tx][ty + i]);
    }
}

// ---------------------------------------------------------------------------
// fc_z: z = h2b @ We3 (+be3 for centers); emits zcb (centers, padded bf16)
// and dzb (neighbors: z_nn - z_c, bias cancels, padded bf16) directly.
// ---------------------------------------------------------------------------
__global__ void __launch_bounds__(256) fc_z(
    const __nv_bfloat16* __restrict__ A,   // g_h2b
    const float* __restrict__ We3, const float* __restrict__ be3, int boff)
{
    __shared__ float As[64][128];
    __shared__ float zc[2][32];
    const int r0 = (blockIdx.x + boff) * 64;
    const int c = threadIdx.x & 31, rg = threadIdx.x >> 5;
    float acc[8] = {};
    for (int kt = 0; kt < H_; kt += 128) {
        __syncthreads();
        for (int l = threadIdx.x; l < 64 * 64; l += 256) {
            int rr = l >> 6, cc2 = l & 63;
            __nv_bfloat162 v =
                *((const __nv_bfloat162*)(A + (size_t)(r0 + rr) * H_ + kt) + cc2);
            *(float2*)&As[rr][cc2 * 2] =
                make_float2(__bfloat162float(v.x), __bfloat162float(v.y));
        }
        __syncthreads();
        for (int k = 0; k < 128; k++) {
            float b = We3[(size_t)(kt + k) * 32 + c];
#pragma unroll
            for (int i = 0; i < 8; i++) acc[i] += As[rg * 8 + i][k] * b;
        }
    }
    if (r0 < BS_) {
        const float bs = be3[c];
#pragma unroll
        for (int i = 0; i < 8; i++) {
            int r = r0 + rg * 8 + i;
            g_zcb[r * 64 + c]      = __float2bfloat16(acc[i] + bs);
            g_zcb[r * 64 + 32 + c] = __float2bfloat16(0.f);
        }
        return;
    }
    // neighbors: local recompute of the 2 relevant center z-rows (no bias)
    const int rn0 = r0 - BS_;
    const int cbase0 = rn0 >> 5;
    {
        const int outi = threadIdx.x >> 2;   // 0..63
        const int sub  = threadIdx.x & 3;
        const int ci = outi >> 5, j = outi & 31;
        const __nv_bfloat16* hr = A + (size_t)(cbase0 + ci) * H_;
        float s = 0.f;
        for (int k = sub * 256; k < sub * 256 + 256; k += 2) {
            __nv_bfloat162 v = *(const __nv_bfloat162*)(hr + k);
            s += __bfloat162float(v.x) * We3[(size_t)k * 32 + j]
               + __bfloat162float(v.y) * We3[(size_t)(k + 1) * 32 + j];
        }
        s += __shfl_xor_sync(0xffffffffu, s, 1);
        s += __shfl_xor_sync(0xffffffffu, s, 2);
        if (sub == 0) zc[ci][j] = s;
    }
    __syncthreads();
#pragma unroll
    for (int i = 0; i < 8; i++) {
        int rn = rn0 + rg * 8 + i;
        int ci = (rn >> 5) - cbase0;
        g_dzb[(size_t)rn * 64 + c]      = __float2bfloat16(acc[i] - zc[ci][c]);
        g_dzb[(size_t)rn * 64 + 32 + c] = __float2bfloat16(0.f);
    }
}

__global__ void final_reduce(float* __restrict__ out)
{
    float s = 0.f;
    for (int i = threadIdx.x; i < 768; i += 256) s += g_lpart[i];
#pragma unroll
    for (int o = 16; o; o >>= 1) s += __shfl_down_sync(0xffffffffu, s, o);
    __shared__ float red[8];
    if ((threadIdx.x & 31) == 0) red[threadIdx.x >> 5] = s;
    __syncthreads();
    if (threadIdx.x == 0) {
        float t = 0.f;
#pragma unroll
        for (int i = 0; i < 8; i++) t += red[i];
        out[0] = t * (1.0f / (float)(BS_ * NN_));
    }
}

// ---------------------------------------------------------------------------
extern "C" void kernel_launch(void* const* d_in, const int* in_sizes, int n_in,
                              void* d_out, int out_size)
{
    const float* x_c = (const float*)d_in[0];
    const float* x_nn = (const float*)d_in[1];
    const float* We1 = (const float*)d_in[2];
    const float* be1 = (const float*)d_in[3];
    const float* We2 = (const float*)d_in[4];
    const float* be2 = (const float*)d_in[5];
    const float* We3 = (const float*)d_in[6];
    const float* be3 = (const float*)d_in[7];
    const float* Wd1 = (const float*)d_in[8];
    const float* bd1 = (const float*)d_in[9];
    const float* Wd2 = (const float*)d_in[10];
    const float* bd2 = (const float*)d_in[11];
    const float* Wd3 = (const float*)d_in[12];
    const float* bd3 = (const float*)d_in[13];
    float* out = (float*)d_out;

    cudaFuncSetAttribute(tgemm<1>, cudaFuncAttributeMaxDynamicSharedMemorySize, SMEM_BYTES);
    cudaFuncSetAttribute(tgemm<3>, cudaFuncAttributeMaxDynamicSharedMemorySize, SMEM_BYTES);
    cudaFuncSetAttribute(tgemm<4>, cudaFuncAttributeMaxDynamicSharedMemorySize, SMEM_BYTES);
    cudaFuncSetAttribute(tgemm<5>, cudaFuncAttributeMaxDynamicSharedMemorySize, SMEM_BYTES);

    __nv_bfloat16 *xa, *h1b, *h2b, *t1, *t2, *We1t, *We2t, *Wd1t, *Wd2t, *Wd3t,
                  *zcb, *dzb, *h1cb, *h2cb;
    float *recon, *w, *lpart;
    cudaGetSymbolAddress((void**)&xa, g_xa);
    cudaGetSymbolAddress((void**)&h1b, g_h1b);
    cudaGetSymbolAddress((void**)&h2b, g_h2b);
    cudaGetSymbolAddress((void**)&t1, g_t1);
    cudaGetSymbolAddress((void**)&t2, g_t2);
    cudaGetSymbolAddress((void**)&We1t, g_We1t);
    cudaGetSymbolAddress((void**)&We2t, g_We2t);
    cudaGetSymbolAddress((void**)&Wd1t, g_Wd1t);
    cudaGetSymbolAddress((void**)&Wd2t, g_Wd2t);
    cudaGetSymbolAddress((void**)&Wd3t, g_Wd3t);
    cudaGetSymbolAddress((void**)&zcb, g_zcb);
    cudaGetSymbolAddress((void**)&dzb, g_dzb);
    cudaGetSymbolAddress((void**)&h1cb, g_h1cb);
    cudaGetSymbolAddress((void**)&h2cb, g_h2cb);
    cudaGetSymbolAddress((void**)&recon, g_recon);
    cudaGetSymbolAddress((void**)&w, g_w);
    cudaGetSymbolAddress((void**)&lpart, g_lpart);

    cudaStream_t sA, sB;
    cudaStreamCreateWithFlags(&sA, cudaStreamNonBlocking);
    cudaStreamCreateWithFlags(&sB, cudaStreamNonBlocking);
    cudaEvent_t ev0, evW1, evW2, evD1, evD2, evD3, evE2A, evFzA,
                evC1, evC2, evRec, evLB;
    cudaEvent_t* evs[] = {&ev0, &evW1, &evW2, &evD1, &evD2, &evD3, &evE2A,
                          &evFzA, &evC1, &evC2, &evRec, &evLB};
    for (int i = 0; i < 12; i++) cudaEventCreateWithFlags(evs[i], cudaEventDisableTiming);

    const dim3 t(128);
    cudaEventRecord(ev0, 0);
    cudaStreamWaitEvent(sA, ev0, 0);
    cudaStreamWaitEvent(sB, ev0, 0);

    // ---- sA: weight transposes, then the center-decoder chain
    transpose_bf16<<<dim3(32, 96), 256, 0, sA>>>(We1, We1t, D_, H_, D_);
    cudaEventRecord(evW1, sA);
    transpose_bf16<<<dim3(32, 32), 256, 0, sA>>>(We2, We2t, H_, H_, H_);
    cudaEventRecord(evW2, sA);
    transpose_bf16<<<dim3(32, 2),  256, 0, sA>>>(Wd1, Wd1t, Z_, H_, 64);
    cudaEventRecord(evD1, sA);
    transpose_bf16<<<dim3(32, 32), 256, 0, sA>>>(Wd2, Wd2t, H_, H_, H_);
    cudaEventRecord(evD2, sA);
    transpose_bf16<<<dim3(96, 32), 256, 0, sA>>>(Wd3, Wd3t, H_, D_, H_);
    cudaEventRecord(evD3, sA);

    // ---- stream 0: half-1 chain (centers + neighbors 0..2047)
    conv_x_w<<<H1ROWS, 256>>>(x_c, x_nn, 0);
    // ---- sB: half-2 chain (neighbors 2048..4095)
    conv_x_w<<<MALL - H1ROWS, 256, 0, sB>>>(x_c, x_nn, H1ROWS);

    cudaStreamWaitEvent(0, evW1, 0);
    tgemm<1><<<dim3(8, 17), t, SMEM_BYTES>>>(xa, We1t, D_, H_, 0, h1b, nullptr,
        be1, nullptr, nullptr, nullptr, nullptr, nullptr);
    cudaStreamWaitEvent(sB, evW1, 0);
    tgemm<1><<<dim3(8, 16), t, SMEM_BYTES, sB>>>(xa + (size_t)H1ROWS * D_, We1t,
        D_, H_, 0, h1b + (size_t)H1ROWS * H_, nullptr,
        be1, nullptr, nullptr, nullptr, nullptr, nullptr);

    cudaStreamWaitEvent(0, evW2, 0);
    tgemm<1><<<dim3(8, 17), t, SMEM_BYTES>>>(h1b, We2t, H_, H_, 0, h2b, nullptr,
        be2, nullptr, nullptr, nullptr, nullptr, nullptr);
    cudaEventRecord(evE2A, 0);
    cudaStreamWaitEvent(sB, evW2, 0);
    tgemm<1><<<dim3(8, 16), t, SMEM_BYTES, sB>>>(h1b + (size_t)H1ROWS * H_, We2t,
        H_, H_, 0, h2b + (size_t)H1ROWS * H_, nullptr,
        be2, nullptr, nullptr, nullptr, nullptr, nullptr);

    fc_z<<<34, 256>>>(h2b, We3, be3, 0);            // centers + neighbors 0..2047
    cudaEventRecord(evFzA, 0);
    cudaStreamWaitEvent(sB, evE2A, 0);              // center h2 rows live in half-1
    fc_z<<<32, 256, 0, sB>>>(h2b, We3, be3, 34);    // neighbors 2048..4095

    // ---- sA: center decoder chain (masks + recon), hidden under jvp chain
    cudaStreamWaitEvent(sA, evFzA, 0);
    tgemm<1><<<dim3(8, 1), t, SMEM_BYTES, sA>>>(zcb, Wd1t, 64, H_, 0, h1cb, nullptr,
        bd1, nullptr, nullptr, nullptr, nullptr, nullptr);
    cudaEventRecord(evC1, sA);
    tgemm<1><<<dim3(8, 1), t, SMEM_BYTES, sA>>>(h1cb, Wd2t, H_, H_, 0, h2cb, nullptr,
        bd2, nullptr, nullptr, nullptr, nullptr, nullptr);
    cudaEventRecord(evC2, sA);
    tgemm<3><<<dim3(24, 1), t, SMEM_BYTES, sA>>>(h2cb, Wd3t, H_, D_, 0, nullptr, recon,
        bd3, nullptr, nullptr, nullptr, nullptr, nullptr);
    cudaEventRecord(evRec, sA);

    // ---- jvp chain (hessian term exactly 0 for ReLU decoder)
    cudaStreamWaitEvent(0, evD1, 0);
    cudaStreamWaitEvent(0, evC1, 0);
    tgemm<4><<<dim3(8, 16), t, SMEM_BYTES>>>(dzb, Wd1t, 64, H_, 0, t1, nullptr,
        nullptr, h1cb, nullptr, nullptr, nullptr, nullptr);
    cudaStreamWaitEvent(sB, evD1, 0);
    cudaStreamWaitEvent(sB, evC1, 0);
    tgemm<4><<<dim3(8, 16), t, SMEM_BYTES, sB>>>(dzb + (size_t)H1NB * 64, Wd1t,
        64, H_, H1NB, t1 + (size_t)H1NB * H_, nullptr,
        nullptr, h1cb, nullptr, nullptr, nullptr, nullptr);

    cudaStreamWaitEvent(0, evD2, 0);
    cudaStreamWaitEvent(0, evC2, 0);
    tgemm<4><<<dim3(8, 16), t, SMEM_BYTES>>>(t1, Wd2t, H_, H_, 0, t2, nullptr,
        nullptr, h2cb, nullptr, nullptr, nullptr, nullptr);
    cudaStreamWaitEvent(sB, evD2, 0);
    cudaStreamWaitEvent(sB, evC2, 0);
    tgemm<4><<<dim3(8, 16), t, SMEM_BYTES, sB>>>(t1 + (size_t)H1NB * H_, Wd2t,
        H_, H_, H1NB, t2 + (size_t)H1NB * H_, nullptr,
        nullptr, h2cb, nullptr, nullptr, nullptr, nullptr);

    // ---- final loss GEMMs
    cudaStreamWaitEvent(0, evD3, 0);
    cudaStreamWaitEvent(0, evRec, 0);
    tgemm<5><<<dim3(24, 16), t, SMEM_BYTES>>>(t2, Wd3t, H_, D_, 0, nullptr, nullptr,
        nullptr, nullptr, x_nn, recon, w, lpart);
    cudaStreamWaitEvent(sB, evD3, 0);
    cudaStreamWaitEvent(sB, evRec, 0);
    tgemm<5><<<dim3(24, 16), t, SMEM_BYTES, sB>>>(t2 + (size_t)H1NB * H_, Wd3t,
        H_, D_, H1NB, nullptr, nullptr,
        nullptr, nullptr, x_nn, recon, w, lpart + 384);
    cudaEventRecord(evLB, sB);

    cudaStreamWaitEvent(0, evLB, 0);
    final_reduce<<<1, 256>>>(out);

    for (int i = 0; i < 12; i++) cudaEventDestroy(*evs[i]);
    cudaStreamDestroy(sA);
    cudaStreamDestroy(sB);
}